// round 14
// baseline (speedup 1.0000x reference)
#include <cuda_runtime.h>
#include <cuda_fp16.h>
#include <cstdint>

// ---------------------------------------------------------------------------
// GAT 4-layer network, N=50000 nodes, E=800000 edges (+ N self-loops).
// dims: 256 -> 32 -> 64 -> 128 -> 128 -> fc 40
// R14: fix R13 sum bug (each group lane already holds the full sum — NO
//      cross-lane reduction). Lanes widened to 8 fp16 cols (Half8): G=8/4/2
//      dsts per warp for COUT=32/64/128. CSR padded x4 with sentinels.
// ---------------------------------------------------------------------------

#define NMAX 50000
#define EMAX 800000
#define CMAX 128
#define CSRMAX (EMAX + 4 * NMAX + 16)

// -------------------- device scratch (allocation-free rule) ---------------
__device__ int      g_src[EMAX];
__device__ int      g_dst[EMAX];
__device__ int      g_cnt[NMAX];          // zero at entry; scan resets it
__device__ int      g_rowptr[NMAX + 1];
__device__ int      g_cursor[NMAX];
__device__ __align__(16) int g_csr_src[CSRMAX];
__device__ __align__(16) __half g_h[(size_t)(NMAX + 1) * CMAX];
__device__ __align__(16) float g_aggA[(size_t)NMAX * CMAX];
__device__ __align__(16) float g_aggB[(size_t)NMAX * CMAX];
__device__ float    g_es[NMAX + 1];       // es[n] = -1e30 sentinel
__device__ float    g_ed[NMAX];

// -------------------- convert + count (detection inlined) -----------------
__global__ void convert_count_kernel(const void* eptr, int E) {
    __shared__ int is64;
    if (threadIdx.x == 0) {
        const int* p = (const int*)eptr;
        int all0 = 1;
#pragma unroll
        for (int k = 1; k < 128; k += 2)
            if (p[k] != 0) all0 = 0;
        is64 = all0;   // int64 little-endian, values < 2^31 -> odd words 0
    }
    __syncthreads();
    int i = blockIdx.x * blockDim.x + threadIdx.x;
    if (i >= E) return;
    int s, d;
    if (is64) {
        const long long* p = (const long long*)eptr;
        s = (int)p[i];
        d = (int)p[E + i];
    } else {
        const int* p = (const int*)eptr;
        s = p[i];
        d = p[E + i];
    }
    g_src[i] = s;
    g_dst[i] = d;
    atomicAdd(&g_cnt[d], 1);
}

// -------------------- single-block scan: rowptr = prefix(pad4(cnt+1)) -----
// Writes sentinel (src=n) pad entries, resets g_cnt, sets es[n].
__global__ void scan_kernel(int n) {
    const int T = 1024;
    int tid = threadIdx.x;
    int C = (n + T - 1) / T;
    int base = tid * C;
    int end = min(base + C, n);

    int s = 0;
    for (int k = base; k < end; k++) {
        int len = g_cnt[k] + 1;
        s += (len + 3) & ~3;
    }

    int lane = tid & 31, w = tid >> 5;
    unsigned full = 0xffffffffu;
    int x = s;
#pragma unroll
    for (int o = 1; o < 32; o <<= 1) {
        int y = __shfl_up_sync(full, x, o);
        if (lane >= o) x += y;
    }
    __shared__ int wsum[32];
    __shared__ int woff[32];
    if (lane == 31) wsum[w] = x;
    __syncthreads();
    if (tid < 32) {
        int v = wsum[tid];
        int xx = v;
#pragma unroll
        for (int o = 1; o < 32; o <<= 1) {
            int y = __shfl_up_sync(full, xx, o);
            if (tid >= o) xx += y;
        }
        woff[tid] = xx - v;
    }
    __syncthreads();
    int running = x - s + woff[w];

    for (int k = base; k < end; k++) {
        int len = g_cnt[k] + 1;
        int plen = (len + 3) & ~3;
        g_rowptr[k] = running;
        g_cursor[k] = running;
        for (int p = running + len; p < running + plen; p++)
            g_csr_src[p] = n;              // sentinel pad edge
        running += plen;
        g_cnt[k] = 0;                      // reset for next replay
    }
    if (end == n && base < n) g_rowptr[n] = running;
    if (tid == 0) g_es[n] = -1e30f;        // sentinel: alpha contribution 0
}

// -------------------- fp16 vector types ------------------------------------
struct __align__(8)  Half4 { __half2 a, b; };
struct __align__(16) Half8 { __half2 a, b, c, d; };

// -------------------- GEMM body (device fn): h=act(in)@W + edot -----------
template <int CIN, int COUT, bool RELU, int R>
__device__ __forceinline__ void gemm_body(const float* __restrict__ in,
                                          const float* __restrict__ W,
                                          const float* __restrict__ as_,
                                          const float* __restrict__ ad_,
                                          int n, int bid, float4* Ws) {
    constexpr int TX = COUT / 4;
    constexpr int TY = 256 / TX;

    int tid = threadIdx.x;
    const float4* W4 = reinterpret_cast<const float4*>(W);
    for (int i = tid; i < CIN * TX; i += 256) Ws[i] = W4[i];
    __syncthreads();

    int tx = tid % TX;
    int ty = tid / TX;
    int row0 = (bid * TY + ty) * R;

    const float4* inp[R];
#pragma unroll
    for (int r = 0; r < R; r++) {
        int rc = min(row0 + r, n - 1);
        inp[r] = reinterpret_cast<const float4*>(in + (size_t)rc * CIN);
    }

    float4 acc[R];
#pragma unroll
    for (int r = 0; r < R; r++) acc[r] = make_float4(0.f, 0.f, 0.f, 0.f);

#pragma unroll 2
    for (int k4 = 0; k4 < CIN / 4; k4++) {
        float4 xv[R];
#pragma unroll
        for (int r = 0; r < R; r++) {
            xv[r] = __ldg(&inp[r][k4]);
            if (RELU) {
                xv[r].x = fmaxf(xv[r].x, 0.f); xv[r].y = fmaxf(xv[r].y, 0.f);
                xv[r].z = fmaxf(xv[r].z, 0.f); xv[r].w = fmaxf(xv[r].w, 0.f);
            }
        }
#pragma unroll
        for (int j = 0; j < 4; j++) {
            float4 w = Ws[(k4 * 4 + j) * TX + tx];
#pragma unroll
            for (int r = 0; r < R; r++) {
                float xs = (j == 0) ? xv[r].x : (j == 1) ? xv[r].y
                         : (j == 2) ? xv[r].z : xv[r].w;
                acc[r].x = fmaf(xs, w.x, acc[r].x);
                acc[r].y = fmaf(xs, w.y, acc[r].y);
                acc[r].z = fmaf(xs, w.z, acc[r].z);
                acc[r].w = fmaf(xs, w.w, acc[r].w);
            }
        }
    }

    // store h as fp16 (4 cols per tx)
    Half4* outh = reinterpret_cast<Half4*>(g_h);
#pragma unroll
    for (int r = 0; r < R; r++) {
        int row = row0 + r;
        if (row < n) {
            Half4 o;
            o.a = __floats2half2_rn(acc[r].x, acc[r].y);
            o.b = __floats2half2_rn(acc[r].z, acc[r].w);
            outh[row * TX + tx] = o;
        }
    }

    // fused edot (fp32): es = h.a_src, ed = h.a_dst
    const float4* as4 = reinterpret_cast<const float4*>(as_);
    const float4* ad4 = reinterpret_cast<const float4*>(ad_);
    float4 av = __ldg(&as4[tx]);
    float4 dv = __ldg(&ad4[tx]);
#pragma unroll
    for (int r = 0; r < R; r++) {
        float ps = acc[r].x * av.x + acc[r].y * av.y
                 + acc[r].z * av.z + acc[r].w * av.w;
        float pd = acc[r].x * dv.x + acc[r].y * dv.y
                 + acc[r].z * dv.z + acc[r].w * dv.w;
#pragma unroll
        for (int off = TX / 2; off > 0; off >>= 1) {
            ps += __shfl_down_sync(0xffffffffu, ps, off, TX);
            pd += __shfl_down_sync(0xffffffffu, pd, off, TX);
        }
        int row = row0 + r;
        if (tx == 0 && row < n) { g_es[row] = ps; g_ed[row] = pd; }
    }
}

// -------------------- standalone GEMM kernel (layers 2-4) -----------------
template <int CIN, int COUT, bool RELU, int R>
__global__ void gemm_kernel(const float* __restrict__ in,
                            const float* __restrict__ W,
                            const float* __restrict__ as_,
                            const float* __restrict__ ad_, int n) {
    extern __shared__ float4 Ws[];
    gemm_body<CIN, COUT, RELU, R>(in, W, as_, ad_, n, blockIdx.x, Ws);
}

// -------------------- fused scatter + gemm1 (independent work) ------------
__global__ void scatter_gemm1_kernel(const float* __restrict__ x,
                                     const float* __restrict__ W1,
                                     const float* __restrict__ a1s,
                                     const float* __restrict__ a1d,
                                     int n, int E, int gemmBlocks) {
    extern __shared__ float4 Ws[];
    if ((int)blockIdx.x < gemmBlocks) {
        gemm_body<256, 32, false, 4>(x, W1, a1s, a1d, n, blockIdx.x, Ws);
    } else {
        int idx = (blockIdx.x - gemmBlocks) * blockDim.x + threadIdx.x;
        if (idx >= E + n) return;
        int s, d;
        if (idx < E) { s = g_src[idx]; d = g_dst[idx]; }
        else         { s = d = idx - E; }
        int pos = atomicAdd(&g_cursor[d], 1);
        g_csr_src[pos] = s;
    }
}

// -------------------- helpers ----------------------------------------------
__device__ __forceinline__ void hfma8(float* a, float x, const Half8& v) {
    float2 f0 = __half22float2(v.a);
    float2 f1 = __half22float2(v.b);
    float2 f2 = __half22float2(v.c);
    float2 f3 = __half22float2(v.d);
    a[0] = fmaf(x, f0.x, a[0]); a[1] = fmaf(x, f0.y, a[1]);
    a[2] = fmaf(x, f1.x, a[2]); a[3] = fmaf(x, f1.y, a[3]);
    a[4] = fmaf(x, f2.x, a[4]); a[5] = fmaf(x, f2.y, a[5]);
    a[6] = fmaf(x, f3.x, a[6]); a[7] = fmaf(x, f3.y, a[7]);
}

// -------------------- fused edge phase: grouped single-pass ----------------
// Each lane holds 8 fp16 columns (one 16B load). L = COUT/8 lanes per dst;
// G = 32/L dsts per warp. All L lanes of a group iterate the SAME edges, so
// each lane's `sum` is already the complete row sum — NO reduction.
// CSR rows padded to x4 with sentinel src=n (es[n]=-1e30 -> weight 0).
template <int COUT>
__global__ void gat_edge_kernel(const float* __restrict__ b,
                                float* __restrict__ agg, int n) {
    constexpr int L = COUT / 8;        // 4 / 8 / 16
    constexpr int G = 32 / L;          // 8 / 4 / 2
    int lane = threadIdx.x & 31;
    int gl   = lane & (L - 1);         // lane within group
    int gid  = lane / L;               // group (dst) within warp
    int w    = threadIdx.x >> 5;
    int d = (blockIdx.x * 8 + w) * G + gid;

    int r0 = 0, r1 = 0;
    float edd = 0.f;
    if (d < n) {
        r0 = g_rowptr[d];
        r1 = g_rowptr[d + 1];
        edd = g_ed[d];
    }

    const Half8* hv = reinterpret_cast<const Half8*>(g_h);  // L per row
    const int4* csr4 = reinterpret_cast<const int4*>(g_csr_src);
    float acc[8] = {0.f, 0.f, 0.f, 0.f, 0.f, 0.f, 0.f, 0.f};
    float sum = 0.f;

#pragma unroll 2
    for (int i = r0; i < r1; i += 4) {
        int4 ss = __ldg(&csr4[i >> 2]);
        float q0 = g_es[ss.x], q1 = g_es[ss.y];
        float q2 = g_es[ss.z], q3 = g_es[ss.w];
        Half8 v0 = hv[ss.x * L + gl];
        Half8 v1 = hv[ss.y * L + gl];
        Half8 v2 = hv[ss.z * L + gl];
        Half8 v3 = hv[ss.w * L + gl];

        float e0 = q0 + edd; e0 = (e0 > 0.f) ? e0 : 0.2f * e0;
        float e1 = q1 + edd; e1 = (e1 > 0.f) ? e1 : 0.2f * e1;
        float e2 = q2 + edd; e2 = (e2 > 0.f) ? e2 : 0.2f * e2;
        float e3 = q3 + edd; e3 = (e3 > 0.f) ? e3 : 0.2f * e3;
        float x0 = __expf(e0), x1 = __expf(e1);
        float x2 = __expf(e2), x3 = __expf(e3);
        sum += (x0 + x1) + (x2 + x3);
        hfma8(acc, x0, v0);
        hfma8(acc, x1, v1);
        hfma8(acc, x2, v2);
        hfma8(acc, x3, v3);
    }

    if (d < n) {
        float inv = 1.0f / sum;
        const float4* bv = reinterpret_cast<const float4*>(b);
        float4 b0 = __ldg(&bv[gl * 2]);
        float4 b1 = __ldg(&bv[gl * 2 + 1]);
        float4 o0, o1;
        o0.x = fmaf(acc[0], inv, b0.x); o0.y = fmaf(acc[1], inv, b0.y);
        o0.z = fmaf(acc[2], inv, b0.z); o0.w = fmaf(acc[3], inv, b0.w);
        o1.x = fmaf(acc[4], inv, b1.x); o1.y = fmaf(acc[5], inv, b1.y);
        o1.z = fmaf(acc[6], inv, b1.z); o1.w = fmaf(acc[7], inv, b1.w);
        float4* av = reinterpret_cast<float4*>(agg);
        av[d * (COUT / 4) + gl * 2]     = o0;
        av[d * (COUT / 4) + gl * 2 + 1] = o1;
    }
}

// -------------------- final FC: out = relu(agg4) @ fcW + fcb --------------
__global__ void fc_kernel(const float* __restrict__ in,
                          const float* __restrict__ fcW,
                          const float* __restrict__ fcb,
                          float* __restrict__ out, int n) {
    __shared__ float Ws[128 * 40];
    int tid = threadIdx.x;                 // blockDim = 320
    for (int i = tid; i < 128 * 40; i += 320) Ws[i] = fcW[i];
    __syncthreads();
    int tx = tid % 40;
    int ty = tid / 40;                     // 8 rows/block
    int row = blockIdx.x * 8 + ty;
    if (row >= n) return;
    const float* irow = in + (size_t)row * 128;
    float acc = 0.f;
#pragma unroll 8
    for (int k = 0; k < 128; k++) {
        float v = fmaxf(irow[k], 0.f);
        acc = fmaf(v, Ws[k * 40 + tx], acc);
    }
    out[(size_t)row * 40 + tx] = acc + fcb[tx];
}

// ---------------------------------------------------------------------------
// host driver
// ---------------------------------------------------------------------------
static inline int ceil_div(int a, int b) { return (a + b - 1) / b; }

template <int CIN, int COUT, bool RELU, int R>
static void launch_gemm(const float* in, const float* W,
                        const float* as_, const float* ad_, int n) {
    constexpr int TX = COUT / 4;
    constexpr int TY = 256 / TX;
    size_t smem = (size_t)CIN * TX * sizeof(float4);
    if (smem > 48 * 1024) {
        cudaFuncSetAttribute(
            (const void*)gemm_kernel<CIN, COUT, RELU, R>,
            cudaFuncAttributeMaxDynamicSharedMemorySize, (int)smem);
    }
    gemm_kernel<CIN, COUT, RELU, R><<<ceil_div(n, TY * R), 256, smem>>>(
        in, W, as_, ad_, n);
}

template <int COUT>
static void launch_edge(const float* b, float* agg, int n) {
    constexpr int G = 32 / (COUT / 8);
    gat_edge_kernel<COUT><<<ceil_div(n, 8 * G), 256>>>(b, agg, n);
}

extern "C" void kernel_launch(void* const* d_in, const int* in_sizes, int n_in,
                              void* d_out, int out_size) {
    const float* x   = (const float*)d_in[0];
    const void*  ei  = d_in[1];
    const float* W1  = (const float*)d_in[2];
    const float* a1s = (const float*)d_in[3];
    const float* a1d = (const float*)d_in[4];
    const float* b1  = (const float*)d_in[5];
    const float* W2  = (const float*)d_in[6];
    const float* a2s = (const float*)d_in[7];
    const float* a2d = (const float*)d_in[8];
    const float* b2  = (const float*)d_in[9];
    const float* W3  = (const float*)d_in[10];
    const float* a3s = (const float*)d_in[11];
    const float* a3d = (const float*)d_in[12];
    const float* b3  = (const float*)d_in[13];
    const float* W4  = (const float*)d_in[14];
    const float* a4s = (const float*)d_in[15];
    const float* a4d = (const float*)d_in[16];
    const float* b4  = (const float*)d_in[17];
    const float* fcW = (const float*)d_in[18];
    const float* fcb = (const float*)d_in[19];

    const int n = in_sizes[0] / 256;
    const int E = in_sizes[1] / 2;
    const int tot = E + n;

    float* aggA; cudaGetSymbolAddress((void**)&aggA, g_aggA);
    float* aggB; cudaGetSymbolAddress((void**)&aggB, g_aggB);

    // launch 1: convert + count (detection inlined; g_cnt is zero at entry)
    convert_count_kernel<<<ceil_div(E, 256), 256>>>(ei, E);
    // launch 2: scan (rowptr = prefix(pad4(cnt+1)); writes sentinels)
    scan_kernel<<<1, 1024>>>(n);
    // launch 3: fused scatter + gemm1
    {
        int gemmBlocks = ceil_div(n, 128);           // TY=32, R=4 -> 128 rows
        int scatBlocks = ceil_div(tot, 256);
        size_t smem = 256 * 8 * sizeof(float4);      // 32 KB
        scatter_gemm1_kernel<<<gemmBlocks + scatBlocks, 256, smem>>>(
            x, W1, a1s, a1d, n, E, gemmBlocks);
    }
    // launch 4 (PROFILED): layer-1 edge kernel (grouped, G=8)
    launch_edge<32>(b1, aggA, n);

    // ---- layer 2: 32 -> 64 ----
    launch_gemm<32, 64, true, 4>(aggA, W2, a2s, a2d, n);
    launch_edge<64>(b2, aggB, n);

    // ---- layer 3: 64 -> 128 ----
    launch_gemm<64, 128, true, 4>(aggB, W3, a3s, a3d, n);
    launch_edge<128>(b3, aggA, n);

    // ---- layer 4: 128 -> 128 ----
    launch_gemm<128, 128, true, 4>(aggA, W4, a4s, a4d, n);
    launch_edge<128>(b4, aggB, n);

    // ---- final fc: relu(agg4) @ fcW + fcb ----
    fc_kernel<<<ceil_div(n, 8), 320>>>(aggB, fcW, fcb, (float*)d_out, n);
}

// round 15
// speedup vs baseline: 1.0395x; 1.0395x over previous
#include <cuda_runtime.h>
#include <cuda_fp16.h>
#include <mma.h>
#include <cstdint>

using namespace nvcuda;

// ---------------------------------------------------------------------------
// GAT 4-layer network, N=50000 nodes, E=800000 edges (+ N self-loops).
// dims: 256 -> 32 -> 64 -> 128 -> 128 -> fc 40
// R15: fp16 wmma for gemm2-4 (fp32 accum), activations fp16 end-to-end,
//      es/ed computed in edge epilogues via precomputed W@a projections
//      (double-buffered). gemm1 stays SIMT fp32 (DRAM-bound). 11 launches.
// ---------------------------------------------------------------------------

#define NMAX 50000
#define NPAD 50048
#define EMAX 800000
#define CMAX 128
#define CSRMAX (EMAX + 4 * NMAX + 16)

// -------------------- device scratch (allocation-free rule) ---------------
__device__ int      g_src[EMAX];
__device__ int      g_dst[EMAX];
__device__ int      g_cnt[NMAX];          // zero at entry; scan resets it
__device__ int      g_rowptr[NMAX + 1];
__device__ int      g_cursor[NMAX];
__device__ __align__(16) int g_csr_src[CSRMAX];
__device__ __align__(16) __half g_h[(size_t)(NMAX + 1) * CMAX];  // row n zero
__device__ __align__(16) __half g_aggAh[(size_t)NPAD * CMAX];    // pad rows 0
__device__ __align__(16) __half g_aggBh[(size_t)NPAD * CMAX];
__device__ float    g_esA[NMAX + 1];      // [n] = -1e30 sentinel
__device__ float    g_edA[NMAX];
__device__ float    g_esB[NMAX + 1];
__device__ float    g_edB[NMAX];
// fp16 weights + attention projections (W @ a)
__device__ __align__(16) __half g_W2h[32 * 64];
__device__ __align__(16) __half g_W3h[64 * 128];
__device__ __align__(16) __half g_W4h[128 * 128];
__device__ __align__(16) float g_wa2s[32], g_wa2d[32];
__device__ __align__(16) float g_wa3s[64], g_wa3d[64];
__device__ __align__(16) float g_wa4s[128], g_wa4d[128];

// -------------------- fp16 vector types ------------------------------------
struct __align__(8)  Half4 { __half2 a, b; };
struct __align__(16) Half8 { __half2 a, b, c, d; };

// -------------------- launch 1: convert+count edges, W->fp16, W@a ---------
__global__ void prep_kernel(const void* eptr, int E, int eBlocks,
                            const float* __restrict__ W2,
                            const float* __restrict__ W3,
                            const float* __restrict__ W4,
                            const float* __restrict__ a2s, const float* __restrict__ a2d,
                            const float* __restrict__ a3s, const float* __restrict__ a3d,
                            const float* __restrict__ a4s, const float* __restrict__ a4d) {
    int bid = blockIdx.x;
    int tid = threadIdx.x;
    if (bid < eBlocks) {
        __shared__ int is64;
        if (tid == 0) {
            const int* p = (const int*)eptr;
            int all0 = 1;
#pragma unroll
            for (int k = 1; k < 128; k += 2)
                if (p[k] != 0) all0 = 0;
            is64 = all0;   // int64 little-endian, values < 2^31 -> odd words 0
        }
        __syncthreads();
        int i = bid * 256 + tid;
        if (i >= E) return;
        int s, d;
        if (is64) {
            const long long* p = (const long long*)eptr;
            s = (int)p[i];
            d = (int)p[E + i];
        } else {
            const int* p = (const int*)eptr;
            s = p[i];
            d = p[E + i];
        }
        g_src[i] = s;
        g_dst[i] = d;
        atomicAdd(&g_cnt[d], 1);
        return;
    }
    int extra = bid - eBlocks;
    if (extra < 104) {
        // W fp32 -> fp16 (2048 + 8192 + 16384 = 26624 elements)
        int idx = extra * 256 + tid;
        if (idx < 2048)        g_W2h[idx] = __float2half(W2[idx]);
        else if (idx < 10240)  g_W3h[idx - 2048] = __float2half(W3[idx - 2048]);
        else if (idx < 26624)  g_W4h[idx - 10240] = __float2half(W4[idx - 10240]);
        return;
    }
    // wa projections: wa = W @ a  (per-row dot)
    for (int i = tid; i < 32; i += 256) {
        float s = 0.f, d = 0.f;
        for (int j = 0; j < 64; j++) {
            float w = W2[i * 64 + j];
            s = fmaf(w, a2s[j], s);
            d = fmaf(w, a2d[j], d);
        }
        g_wa2s[i] = s; g_wa2d[i] = d;
    }
    for (int i = tid; i < 64; i += 256) {
        float s = 0.f, d = 0.f;
        for (int j = 0; j < 128; j++) {
            float w = W3[i * 128 + j];
            s = fmaf(w, a3s[j], s);
            d = fmaf(w, a3d[j], d);
        }
        g_wa3s[i] = s; g_wa3d[i] = d;
    }
    for (int i = tid; i < 128; i += 256) {
        float s = 0.f, d = 0.f;
        for (int j = 0; j < 128; j++) {
            float w = W4[i * 128 + j];
            s = fmaf(w, a4s[j], s);
            d = fmaf(w, a4d[j], d);
        }
        g_wa4s[i] = s; g_wa4d[i] = d;
    }
}

// -------------------- launch 2: scan (pad4 rows, sentinels, reset) --------
__global__ void scan_kernel(int n) {
    const int T = 1024;
    int tid = threadIdx.x;
    int C = (n + T - 1) / T;
    int base = tid * C;
    int end = min(base + C, n);

    int s = 0;
    for (int k = base; k < end; k++) {
        int len = g_cnt[k] + 1;
        s += (len + 3) & ~3;
    }

    int lane = tid & 31, w = tid >> 5;
    unsigned full = 0xffffffffu;
    int x = s;
#pragma unroll
    for (int o = 1; o < 32; o <<= 1) {
        int y = __shfl_up_sync(full, x, o);
        if (lane >= o) x += y;
    }
    __shared__ int wsum[32];
    __shared__ int woff[32];
    if (lane == 31) wsum[w] = x;
    __syncthreads();
    if (tid < 32) {
        int v = wsum[tid];
        int xx = v;
#pragma unroll
        for (int o = 1; o < 32; o <<= 1) {
            int y = __shfl_up_sync(full, xx, o);
            if (tid >= o) xx += y;
        }
        woff[tid] = xx - v;
    }
    __syncthreads();
    int running = x - s + woff[w];

    for (int k = base; k < end; k++) {
        int len = g_cnt[k] + 1;
        int plen = (len + 3) & ~3;
        g_rowptr[k] = running;
        g_cursor[k] = running;
        for (int p = running + len; p < running + plen; p++)
            g_csr_src[p] = n;              // sentinel pad edge
        running += plen;
        g_cnt[k] = 0;                      // reset for next replay
    }
    if (end == n && base < n) g_rowptr[n] = running;
    if (tid == 0) { g_esA[n] = -1e30f; g_esB[n] = -1e30f; }
}

// -------------------- SIMT gemm1 body: h1=x@W1 (fp16 out) + es/ed ---------
template <int CIN, int COUT, int R>
__device__ __forceinline__ void gemm_body(const float* __restrict__ in,
                                          const float* __restrict__ W,
                                          const float* __restrict__ as_,
                                          const float* __restrict__ ad_,
                                          float* __restrict__ esOut,
                                          float* __restrict__ edOut,
                                          int n, int bid, float4* Ws) {
    constexpr int TX = COUT / 4;
    constexpr int TY = 256 / TX;

    int tid = threadIdx.x;
    const float4* W4 = reinterpret_cast<const float4*>(W);
    for (int i = tid; i < CIN * TX; i += 256) Ws[i] = W4[i];
    __syncthreads();

    int tx = tid % TX;
    int ty = tid / TX;
    int row0 = (bid * TY + ty) * R;

    const float4* inp[R];
#pragma unroll
    for (int r = 0; r < R; r++) {
        int rc = min(row0 + r, n - 1);
        inp[r] = reinterpret_cast<const float4*>(in + (size_t)rc * CIN);
    }

    float4 acc[R];
#pragma unroll
    for (int r = 0; r < R; r++) acc[r] = make_float4(0.f, 0.f, 0.f, 0.f);

#pragma unroll 2
    for (int k4 = 0; k4 < CIN / 4; k4++) {
        float4 xv[R];
#pragma unroll
        for (int r = 0; r < R; r++) xv[r] = __ldg(&inp[r][k4]);
#pragma unroll
        for (int j = 0; j < 4; j++) {
            float4 w = Ws[(k4 * 4 + j) * TX + tx];
#pragma unroll
            for (int r = 0; r < R; r++) {
                float xs = (j == 0) ? xv[r].x : (j == 1) ? xv[r].y
                         : (j == 2) ? xv[r].z : xv[r].w;
                acc[r].x = fmaf(xs, w.x, acc[r].x);
                acc[r].y = fmaf(xs, w.y, acc[r].y);
                acc[r].z = fmaf(xs, w.z, acc[r].z);
                acc[r].w = fmaf(xs, w.w, acc[r].w);
            }
        }
    }

    // store h as fp16
    Half4* outh = reinterpret_cast<Half4*>(g_h);
#pragma unroll
    for (int r = 0; r < R; r++) {
        int row = row0 + r;
        if (row < n) {
            Half4 o;
            o.a = __floats2half2_rn(acc[r].x, acc[r].y);
            o.b = __floats2half2_rn(acc[r].z, acc[r].w);
            outh[row * TX + tx] = o;
        }
    }

    // fused edot (fp32): es = h.a_src, ed = h.a_dst
    const float4* as4 = reinterpret_cast<const float4*>(as_);
    const float4* ad4 = reinterpret_cast<const float4*>(ad_);
    float4 av = __ldg(&as4[tx]);
    float4 dv = __ldg(&ad4[tx]);
#pragma unroll
    for (int r = 0; r < R; r++) {
        float ps = acc[r].x * av.x + acc[r].y * av.y
                 + acc[r].z * av.z + acc[r].w * av.w;
        float pd = acc[r].x * dv.x + acc[r].y * dv.y
                 + acc[r].z * dv.z + acc[r].w * dv.w;
#pragma unroll
        for (int off = TX / 2; off > 0; off >>= 1) {
            ps += __shfl_down_sync(0xffffffffu, ps, off, TX);
            pd += __shfl_down_sync(0xffffffffu, pd, off, TX);
        }
        int row = row0 + r;
        if (tx == 0 && row < n) { esOut[row] = ps; edOut[row] = pd; }
    }
}

// -------------------- launch 3: fused scatter + gemm1 ---------------------
__global__ void scatter_gemm1_kernel(const float* __restrict__ x,
                                     const float* __restrict__ W1,
                                     const float* __restrict__ a1s,
                                     const float* __restrict__ a1d,
                                     int n, int E, int gemmBlocks) {
    extern __shared__ float4 Ws[];
    if ((int)blockIdx.x < gemmBlocks) {
        gemm_body<256, 32, 4>(x, W1, a1s, a1d, g_esA, g_edA, n, blockIdx.x, Ws);
    } else {
        int idx = (blockIdx.x - gemmBlocks) * blockDim.x + threadIdx.x;
        if (idx >= E + n) return;
        int s, d;
        if (idx < E) { s = g_src[idx]; d = g_dst[idx]; }
        else         { s = d = idx - E; }
        int pos = atomicAdd(&g_cursor[d], 1);
        g_csr_src[pos] = s;
    }
}

// -------------------- wmma GEMM: h = A(fp16) @ Wh(fp16), fp32 accum -------
template <int CIN, int COUT>
__global__ void gemm_wmma_kernel(const __half* __restrict__ A,
                                 const __half* __restrict__ Wh, int n) {
    constexpr int NT = COUT / 16;
    extern __shared__ __half sm[];                 // W: CIN*COUT halfs
    float* stage = reinterpret_cast<float*>(sm + CIN * COUT);  // 8*16*COUT fl

    int tid = threadIdx.x;
    int w = tid >> 5;
    int lane = tid & 31;

    const int4* Wv = reinterpret_cast<const int4*>(Wh);
    int4* smv = reinterpret_cast<int4*>(sm);
    for (int i = tid; i < CIN * COUT / 8; i += 256) smv[i] = Wv[i];
    __syncthreads();

    int row0 = blockIdx.x * 128 + w * 16;

    wmma::fragment<wmma::accumulator, 16, 16, 16, float> acc[NT];
#pragma unroll
    for (int t = 0; t < NT; t++) wmma::fill_fragment(acc[t], 0.0f);

#pragma unroll
    for (int k = 0; k < CIN; k += 16) {
        wmma::fragment<wmma::matrix_a, 16, 16, 16, __half, wmma::row_major> af;
        wmma::load_matrix_sync(af, A + (size_t)row0 * CIN + k, CIN);
#pragma unroll
        for (int t = 0; t < NT; t++) {
            wmma::fragment<wmma::matrix_b, 16, 16, 16, __half, wmma::row_major> bf;
            wmma::load_matrix_sync(bf, sm + k * COUT + t * 16, COUT);
            wmma::mma_sync(acc[t], af, bf, acc[t]);
        }
    }

    // stage fp32 per-warp, convert to fp16 h (rows < n only; row n stays 0)
    float* st = stage + w * 16 * COUT;
#pragma unroll
    for (int t = 0; t < NT; t++)
        wmma::store_matrix_sync(st + t * 16, acc[t], COUT, wmma::mem_row_major);
    __syncwarp();

    Half8* outh = reinterpret_cast<Half8*>(g_h);
    for (int idx = lane; idx < 16 * (COUT / 8); idx += 32) {
        int r = idx / (COUT / 8);
        int c8 = idx % (COUT / 8);
        int row = row0 + r;
        if (row < n) {
            const float* p = st + r * COUT + c8 * 8;
            Half8 o;
            o.a = __floats2half2_rn(p[0], p[1]);
            o.b = __floats2half2_rn(p[2], p[3]);
            o.c = __floats2half2_rn(p[4], p[5]);
            o.d = __floats2half2_rn(p[6], p[7]);
            outh[row * (COUT / 8) + c8] = o;
        }
    }
}

// -------------------- helpers ----------------------------------------------
__device__ __forceinline__ void hfma8(float* a, float x, const Half8& v) {
    float2 f0 = __half22float2(v.a);
    float2 f1 = __half22float2(v.b);
    float2 f2 = __half22float2(v.c);
    float2 f3 = __half22float2(v.d);
    a[0] = fmaf(x, f0.x, a[0]); a[1] = fmaf(x, f0.y, a[1]);
    a[2] = fmaf(x, f1.x, a[2]); a[3] = fmaf(x, f1.y, a[3]);
    a[4] = fmaf(x, f2.x, a[4]); a[5] = fmaf(x, f2.y, a[5]);
    a[6] = fmaf(x, f3.x, a[6]); a[7] = fmaf(x, f3.y, a[7]);
}

// -------------------- edge kernel: softmax-agg + fp16 relu out + dots -----
// Grouped: L = COUT/8 lanes per dst, G = 32/L dsts per warp. Each lane's
// sum is the complete row sum (no reduction). Epilogue writes relu(out) as
// fp16 (next GEMM's A) and, if DOTS, es/ed for the NEXT layer via W@a
// projections (cross-lane reduce over the L group lanes).
template <int COUT, bool DOTS>
__global__ void gat_edge_kernel(const float* __restrict__ b,
                                const float* __restrict__ es,
                                const float* __restrict__ ed,
                                float* __restrict__ esN,
                                float* __restrict__ edN,
                                const float* __restrict__ was,
                                const float* __restrict__ wad,
                                __half* __restrict__ aggh, int n) {
    constexpr int L = COUT / 8;        // 4 / 8 / 16
    constexpr int G = 32 / L;          // 8 / 4 / 2
    const unsigned full = 0xffffffffu;
    int lane = threadIdx.x & 31;
    int gl   = lane & (L - 1);
    int gid  = lane / L;
    int w    = threadIdx.x >> 5;
    int d = (blockIdx.x * 8 + w) * G + gid;

    int r0 = 0, r1 = 0;
    float edd = 0.f;
    if (d < n) {
        r0 = g_rowptr[d];
        r1 = g_rowptr[d + 1];
        edd = ed[d];
    }

    const Half8* hv = reinterpret_cast<const Half8*>(g_h);
    const int4* csr4 = reinterpret_cast<const int4*>(g_csr_src);
    float acc[8] = {0.f, 0.f, 0.f, 0.f, 0.f, 0.f, 0.f, 0.f};
    float sum = 0.f;

#pragma unroll 2
    for (int i = r0; i < r1; i += 4) {
        int4 ss = __ldg(&csr4[i >> 2]);
        float q0 = es[ss.x], q1 = es[ss.y];
        float q2 = es[ss.z], q3 = es[ss.w];
        Half8 v0 = hv[ss.x * L + gl];
        Half8 v1 = hv[ss.y * L + gl];
        Half8 v2 = hv[ss.z * L + gl];
        Half8 v3 = hv[ss.w * L + gl];

        float e0 = q0 + edd; e0 = (e0 > 0.f) ? e0 : 0.2f * e0;
        float e1 = q1 + edd; e1 = (e1 > 0.f) ? e1 : 0.2f * e1;
        float e2 = q2 + edd; e2 = (e2 > 0.f) ? e2 : 0.2f * e2;
        float e3 = q3 + edd; e3 = (e3 > 0.f) ? e3 : 0.2f * e3;
        float x0 = __expf(e0), x1 = __expf(e1);
        float x2 = __expf(e2), x3 = __expf(e3);
        sum += (x0 + x1) + (x2 + x3);
        hfma8(acc, x0, v0);
        hfma8(acc, x1, v1);
        hfma8(acc, x2, v2);
        hfma8(acc, x3, v3);
    }

    float o[8];
    float inv = 1.0f / sum;
    if (d < n) {
        const float4* bv = reinterpret_cast<const float4*>(b);
        float4 b0 = __ldg(&bv[gl * 2]);
        float4 b1 = __ldg(&bv[gl * 2 + 1]);
        o[0] = fmaxf(fmaf(acc[0], inv, b0.x), 0.f);
        o[1] = fmaxf(fmaf(acc[1], inv, b0.y), 0.f);
        o[2] = fmaxf(fmaf(acc[2], inv, b0.z), 0.f);
        o[3] = fmaxf(fmaf(acc[3], inv, b0.w), 0.f);
        o[4] = fmaxf(fmaf(acc[4], inv, b1.x), 0.f);
        o[5] = fmaxf(fmaf(acc[5], inv, b1.y), 0.f);
        o[6] = fmaxf(fmaf(acc[6], inv, b1.z), 0.f);
        o[7] = fmaxf(fmaf(acc[7], inv, b1.w), 0.f);
        Half8 oh;
        oh.a = __floats2half2_rn(o[0], o[1]);
        oh.b = __floats2half2_rn(o[2], o[3]);
        oh.c = __floats2half2_rn(o[4], o[5]);
        oh.d = __floats2half2_rn(o[6], o[7]);
        reinterpret_cast<Half8*>(aggh)[d * L + gl] = oh;
    } else {
#pragma unroll
        for (int j = 0; j < 8; j++) o[j] = 0.f;
    }

    if (DOTS) {
        const float4* wsv = reinterpret_cast<const float4*>(was);
        const float4* wdv = reinterpret_cast<const float4*>(wad);
        float4 s0 = __ldg(&wsv[gl * 2]),  s1 = __ldg(&wsv[gl * 2 + 1]);
        float4 d0 = __ldg(&wdv[gl * 2]),  d1 = __ldg(&wdv[gl * 2 + 1]);
        float ps = o[0] * s0.x + o[1] * s0.y + o[2] * s0.z + o[3] * s0.w
                 + o[4] * s1.x + o[5] * s1.y + o[6] * s1.z + o[7] * s1.w;
        float pd = o[0] * d0.x + o[1] * d0.y + o[2] * d0.z + o[3] * d0.w
                 + o[4] * d1.x + o[5] * d1.y + o[6] * d1.z + o[7] * d1.w;
#pragma unroll
        for (int off = L >> 1; off; off >>= 1) {
            ps += __shfl_xor_sync(full, ps, off);
            pd += __shfl_xor_sync(full, pd, off);
        }
        if (d < n && gl == 0) { esN[d] = ps; edN[d] = pd; }
    }
}

// -------------------- final FC: out = agg4(fp16, relu'd) @ fcW + fcb ------
__global__ void fc_kernel(const __half* __restrict__ in,
                          const float* __restrict__ fcW,
                          const float* __restrict__ fcb,
                          float* __restrict__ out, int n) {
    __shared__ float Ws[128 * 40];
    int tid = threadIdx.x;                 // blockDim = 320
    for (int i = tid; i < 128 * 40; i += 320) Ws[i] = fcW[i];
    __syncthreads();
    int tx = tid % 40;
    int ty = tid / 40;                     // 8 rows/block
    int row = blockIdx.x * 8 + ty;
    if (row >= n) return;
    const __half* irow = in + (size_t)row * 128;
    float acc = 0.f;
#pragma unroll 8
    for (int k = 0; k < 128; k++) {
        float v = __half2float(irow[k]);   // already relu'd
        acc = fmaf(v, Ws[k * 40 + tx], acc);
    }
    out[(size_t)row * 40 + tx] = acc + fcb[tx];
}

// ---------------------------------------------------------------------------
// host driver
// ---------------------------------------------------------------------------
static inline int ceil_div(int a, int b) { return (a + b - 1) / b; }

template <int CIN, int COUT>
static void launch_wmma(const __half* A, const __half* Wh, int n) {
    size_t smem = (size_t)CIN * COUT * 2 + (size_t)8 * 16 * COUT * 4;
    if (smem > 48 * 1024) {
        cudaFuncSetAttribute((const void*)gemm_wmma_kernel<CIN, COUT>,
                             cudaFuncAttributeMaxDynamicSharedMemorySize,
                             (int)smem);
    }
    gemm_wmma_kernel<CIN, COUT><<<ceil_div(n, 128), 256, smem>>>(A, Wh, n);
}

template <int COUT, bool DOTS>
static void launch_edge(const float* b, const float* es, const float* ed,
                        float* esN, float* edN,
                        const float* was, const float* wad,
                        __half* aggh, int n) {
    constexpr int G = 32 / (COUT / 8);
    gat_edge_kernel<COUT, DOTS><<<ceil_div(n, 8 * G), 256>>>(
        b, es, ed, esN, edN, was, wad, aggh, n);
}

extern "C" void kernel_launch(void* const* d_in, const int* in_sizes, int n_in,
                              void* d_out, int out_size) {
    const float* x   = (const float*)d_in[0];
    const void*  ei  = d_in[1];
    const float* W1  = (const float*)d_in[2];
    const float* a1s = (const float*)d_in[3];
    const float* a1d = (const float*)d_in[4];
    const float* b1  = (const float*)d_in[5];
    const float* W2  = (const float*)d_in[6];
    const float* a2s = (const float*)d_in[7];
    const float* a2d = (const float*)d_in[8];
    const float* b2  = (const float*)d_in[9];
    const float* W3  = (const float*)d_in[10];
    const float* a3s = (const float*)d_in[11];
    const float* a3d = (const float*)d_in[12];
    const float* b3  = (const float*)d_in[13];
    const float* W4  = (const float*)d_in[14];
    const float* a4s = (const float*)d_in[15];
    const float* a4d = (const float*)d_in[16];
    const float* b4  = (const float*)d_in[17];
    const float* fcW = (const float*)d_in[18];
    const float* fcb = (const float*)d_in[19];

    const int n = in_sizes[0] / 256;
    const int E = in_sizes[1] / 2;
    const int tot = E + n;

    __half *aggAh, *aggBh, *W2h, *W3h, *W4h;
    float *esA, *edA, *esB, *edB;
    float *wa2s, *wa2d, *wa3s, *wa3d, *wa4s, *wa4d;
    cudaGetSymbolAddress((void**)&aggAh, g_aggAh);
    cudaGetSymbolAddress((void**)&aggBh, g_aggBh);
    cudaGetSymbolAddress((void**)&W2h, g_W2h);
    cudaGetSymbolAddress((void**)&W3h, g_W3h);
    cudaGetSymbolAddress((void**)&W4h, g_W4h);
    cudaGetSymbolAddress((void**)&esA, g_esA);
    cudaGetSymbolAddress((void**)&edA, g_edA);
    cudaGetSymbolAddress((void**)&esB, g_esB);
    cudaGetSymbolAddress((void**)&edB, g_edB);
    cudaGetSymbolAddress((void**)&wa2s, g_wa2s);
    cudaGetSymbolAddress((void**)&wa2d, g_wa2d);
    cudaGetSymbolAddress((void**)&wa3s, g_wa3s);
    cudaGetSymbolAddress((void**)&wa3d, g_wa3d);
    cudaGetSymbolAddress((void**)&wa4s, g_wa4s);
    cudaGetSymbolAddress((void**)&wa4d, g_wa4d);

    int eBlocks = ceil_div(E, 256);

    // launch 1: edge convert+count, W->fp16, wa projections
    prep_kernel<<<eBlocks + 105, 256>>>(ei, E, eBlocks, W2, W3, W4,
                                        a2s, a2d, a3s, a3d, a4s, a4d);
    // launch 2: scan (rowptr, sentinels, reset)
    scan_kernel<<<1, 1024>>>(n);
    // launch 3: fused scatter + gemm1 (SIMT fp32, writes h fp16 + esA/edA)
    {
        int gemmBlocks = ceil_div(n, 128);           // TY=32, R=4
        int scatBlocks = ceil_div(tot, 256);
        size_t smem = 256 * 8 * sizeof(float4);      // 32 KB (CIN=256,TX=8)
        scatter_gemm1_kernel<<<gemmBlocks + scatBlocks, 256, smem>>>(
            x, W1, a1s, a1d, n, E, gemmBlocks);
    }
    // launch 4 (PROFILED): edge1 — reads esA, writes aggAh + esB/edB
    launch_edge<32, true>(b1, esA, edA, esB, edB, wa2s, wa2d, aggAh, n);

    // layer 2: gemm (wmma) + edge
    launch_wmma<32, 64>(aggAh, W2h, n);
    launch_edge<64, true>(b2, esB, edB, esA, edA, wa3s, wa3d, aggBh, n);

    // layer 3
    launch_wmma<64, 128>(aggBh, W3h, n);
    launch_edge<128, true>(b3, esA, edA, esB, edB, wa4s, wa4d, aggAh, n);

    // layer 4
    launch_wmma<128, 128>(aggAh, W4h, n);
    launch_edge<128, false>(b4, esB, edB, nullptr, nullptr, nullptr, nullptr,
                            aggBh, n);

    // final fc
    fc_kernel<<<ceil_div(n, 8), 320>>>(aggBh, fcW, fcb, (float*)d_out, n);
}